// round 11
// baseline (speedup 1.0000x reference)
#include <cuda_runtime.h>
#include <cuda_fp16.h>
#include <math.h>
#include <cstdint>

#define BB 4
#define NN 4096
#define CC 1024
#define HH 16
#define DD 64
#define MTOT (BB*NN)        // 16384
#define QKVC (3*CC)         // 3072
#define KDIM 1024
#define KVCHUNK 8

// ---------------- scratch (device globals; allocation-free) ----------------
__device__ __half g_qkvh[(size_t)MTOT * QKVC];   // fp16 qkv (post-elu q,k; raw v)
__device__ __half g_xh[(size_t)MTOT * CC];
__device__ __half g_attn_h[(size_t)MTOT * CC];
__device__ __half g_wqkvT_hi[(size_t)QKVC * KDIM];
__device__ __half g_wqkvT_lo[(size_t)QKVC * KDIM];
__device__ __half g_wprojT_hi[(size_t)CC * KDIM];
__device__ __half g_wprojT_lo[(size_t)CC * KDIM];
__device__ float g_kvp[KVCHUNK * BB*HH*DD*DD];
__device__ float g_ksump[KVCHUNK * BB*HH*DD];
__device__ float g_kv[BB*HH*DD*DD];
__device__ float g_ksum[BB*HH*DD];

// ---------------- PTX helpers (baseline sm_80-class; assemble on sm_103) ----
__device__ __forceinline__ uint32_t smem_u32(const void* p) {
    uint32_t a;
    asm("{ .reg .u64 t; cvta.to.shared.u64 t, %1; cvt.u32.u64 %0, t; }" : "=r"(a) : "l"(p));
    return a;
}
__device__ __forceinline__ void cp16(uint32_t s, const void* g) {
    asm volatile("cp.async.cg.shared.global [%0], [%1], 16;" :: "r"(s), "l"(g));
}
#define CP_COMMIT() asm volatile("cp.async.commit_group;" ::: "memory")
#define CP_WAIT1()  asm volatile("cp.async.wait_group 1;" ::: "memory")

__device__ __forceinline__ void ldmx4(uint32_t* r, uint32_t addr) {
    asm volatile("ldmatrix.sync.aligned.m8n8.x4.shared.b16 {%0,%1,%2,%3}, [%4];"
                 : "=r"(r[0]), "=r"(r[1]), "=r"(r[2]), "=r"(r[3]) : "r"(addr));
}
__device__ __forceinline__ void mma16816(float* d, const uint32_t* a, const uint32_t* b) {
    asm volatile("mma.sync.aligned.m16n8k16.row.col.f32.f16.f16.f32 "
                 "{%0,%1,%2,%3}, {%4,%5,%6,%7}, {%8,%9}, {%0,%1,%2,%3};"
                 : "+f"(d[0]), "+f"(d[1]), "+f"(d[2]), "+f"(d[3])
                 : "r"(a[0]), "r"(a[1]), "r"(a[2]), "r"(a[3]), "r"(b[0]), "r"(b[1]));
}

// ---------------- converts ----------------
__global__ void cvt_f16(const float2* __restrict__ in, __half2* __restrict__ out, size_t n2) {
    size_t i = (size_t)blockIdx.x * blockDim.x + threadIdx.x;
    if (i >= n2) return;
    float2 v = in[i];
    out[i] = __floats2half2_rn(v.x, v.y);
}

// transpose + split: in [K][N] fp32 -> out hi/lo [N][K] fp16
__global__ __launch_bounds__(256) void transpose_cvt(
    const float* __restrict__ in, __half* __restrict__ hi,
    __half* __restrict__ lo, int K, int N) {
    __shared__ float t[32][33];
    int n0 = blockIdx.x * 32, k0 = blockIdx.y * 32;
    int tx = threadIdx.x & 31, ty = threadIdx.x >> 5;
    #pragma unroll
    for (int i = 0; i < 4; i++)
        t[ty + 8*i][tx] = in[(size_t)(k0 + ty + 8*i) * N + n0 + tx];
    __syncthreads();
    #pragma unroll
    for (int i = 0; i < 4; i++) {
        float v = t[tx][ty + 8*i];
        size_t o = (size_t)(n0 + ty + 8*i) * K + k0 + tx;
        __half h = __float2half_rn(v);
        hi[o] = h;
        lo[o] = __float2half_rn(v - __half2float(h));
    }
}

// ---------------- HMMA fp16 2-term GEMM: C[M,N] = A[M,K] @ (Bh+Bl)[N,K]^T ----
// Block tile 256x128, BK=64, 8 warps (4M x 2N), warp tile 64x64, 3-stage cp.async.
#define KITERS (KDIM / 64)       // 16
#define AHB 32768u               // A: 256 rows x 128B
#define BHB 16384u               // Bh: 128 rows x 128B
#define STAGEB (AHB + 2u*BHB)    // 65536
#define GEMM_SMEM (3 * 65536)    // 196608

template<bool ELU, bool BIAS, bool OUT16>
__global__ __launch_bounds__(256, 1) void gemm_mma(
    const __half* __restrict__ A,
    const __half* __restrict__ Bhi, const __half* __restrict__ Blo,
    const float* __restrict__ bias, void* __restrict__ Cv, int N)
{
    extern __shared__ char sm[];
    const uint32_t sb = smem_u32(sm);
    const int tid = threadIdx.x;
    const int lane = tid & 31, wid = tid >> 5;
    const int wm = (wid >> 1) * 64;
    const int wn = (wid & 1) * 64;
    const int m0 = blockIdx.y * 256, n0 = blockIdx.x * 128;

    // ---- cp.async geometry: 128B rows, 8 chunks of 16B, 8-way XOR swizzle ----
    const int ch = tid & 7;
    const int rbase = tid >> 3;
    uint32_t soA[8], soB[4]; size_t gA[8], gB[4];
    #pragma unroll
    for (int i = 0; i < 8; i++) {
        int r = rbase + 32 * i;
        soA[i] = (uint32_t)(r * 128) + (uint32_t)((ch ^ (r & 7)) << 4);
        gA[i] = (size_t)(m0 + r) * KDIM + ch * 8;
    }
    #pragma unroll
    for (int i = 0; i < 4; i++) {
        int r = rbase + 32 * i;
        soB[i] = (uint32_t)(r * 128) + (uint32_t)((ch ^ (r & 7)) << 4);
        gB[i] = (size_t)(n0 + r) * KDIM + ch * 8;
    }

    // ---- ldmatrix geometry ----
    int ra[4], rb[4];
    #pragma unroll
    for (int mt = 0; mt < 4; mt++) ra[mt] = wm + mt * 16 + (lane & 15);
    #pragma unroll
    for (int np = 0; np < 4; np++)
        rb[np] = wn + np * 16 + (lane & 7) + ((lane & 16) ? 8 : 0);
    const int caH = lane >> 4;
    const int cbH = (lane >> 3) & 1;

    float acc[4][8][4];
    #pragma unroll
    for (int mt = 0; mt < 4; mt++)
        #pragma unroll
        for (int nt = 0; nt < 8; nt++)
            #pragma unroll
            for (int j = 0; j < 4; j++) acc[mt][nt][j] = 0.f;

    auto issue = [&](int s) {
        if (s < KITERS) {
            uint32_t st = sb + (uint32_t)(s % 3) * STAGEB;
            size_t ko = (size_t)s * 64;
            #pragma unroll
            for (int i = 0; i < 8; i++)
                cp16(st + soA[i], A + gA[i] + ko);
            #pragma unroll
            for (int i = 0; i < 4; i++) {
                cp16(st + AHB + soB[i],       Bhi + gB[i] + ko);
                cp16(st + AHB + BHB + soB[i], Blo + gB[i] + ko);
            }
        }
        CP_COMMIT();
    };

    issue(0);
    issue(1);

    for (int s = 0; s < KITERS; s++) {
        CP_WAIT1();
        __syncthreads();
        issue(s + 2);

        const uint32_t st = sb + (uint32_t)(s % 3) * STAGEB;
        #pragma unroll
        for (int ks = 0; ks < 4; ks++) {
            uint32_t ah[4][4];
            #pragma unroll
            for (int mt = 0; mt < 4; mt++) {
                uint32_t c = (uint32_t)(ks * 2 + caH);
                uint32_t off = (uint32_t)(ra[mt] * 128) + ((c ^ (ra[mt] & 7)) << 4);
                ldmx4(ah[mt], st + off);
            }
            #pragma unroll
            for (int np = 0; np < 4; np++) {
                uint32_t c = (uint32_t)(ks * 2 + cbH);
                uint32_t off = (uint32_t)(rb[np] * 128) + ((c ^ (rb[np] & 7)) << 4);
                uint32_t bh[4], bl[4];
                ldmx4(bh, st + AHB + off);
                ldmx4(bl, st + AHB + BHB + off);
                #pragma unroll
                for (int mt = 0; mt < 4; mt++) {
                    mma16816(acc[mt][2*np  ], ah[mt], bh + 0);
                    mma16816(acc[mt][2*np  ], ah[mt], bl + 0);
                    mma16816(acc[mt][2*np+1], ah[mt], bh + 2);
                    mma16816(acc[mt][2*np+1], ah[mt], bl + 2);
                }
            }
        }
    }

    // ---- epilogue ----
    #pragma unroll
    for (int mt = 0; mt < 4; mt++) {
        #pragma unroll
        for (int nt = 0; nt < 8; nt++) {
            int row = m0 + wm + mt * 16 + (lane >> 2);
            int col = n0 + wn + nt * 8 + (lane & 3) * 2;
            #pragma unroll
            for (int half = 0; half < 2; half++) {
                int r = row + half * 8;
                float v0 = acc[mt][nt][half * 2 + 0];
                float v1 = acc[mt][nt][half * 2 + 1];
                if (ELU) {
                    if (col < 2048)     v0 = (v0 > 0.f) ? (v0 + 1.f) : expf(v0);
                    if (col + 1 < 2048) v1 = (v1 > 0.f) ? (v1 + 1.f) : expf(v1);
                }
                if (BIAS) { v0 += bias[col]; v1 += bias[col + 1]; }
                if (OUT16) {
                    __half* Ch = (__half*)Cv;
                    *(__half2*)(Ch + (size_t)r * N + col) = __floats2half2_rn(v0, v1);
                } else {
                    float* Cf = (float*)Cv;
                    float2 o; o.x = v0; o.y = v1;
                    *(float2*)(Cf + (size_t)r * N + col) = o;
                }
            }
        }
    }
}

// ---------------- attention: kv partial over N-chunk (fp16 in, fp32 accum) ----
__global__ __launch_bounds__(256) void kv_part_kernel(
    const __half* __restrict__ qkvh, float* __restrict__ kvp, float* __restrict__ ksump)
{
    const int bx = blockIdx.x;          // 0..511
    const int bh = bx >> 3, chunk = bx & 7;
    const int b = bh >> 4, h = bh & 15;
    const int nbeg = chunk * (NN / KVCHUNK), nend = nbeg + NN / KVCHUNK;
    const __half* kbase = qkvh + (size_t)b * NN * QKVC + CC + h * DD;
    const __half* vbase = qkvh + (size_t)b * NN * QKVC + 2 * CC + h * DD;

    __shared__ float ks[32][64];
    __shared__ float vs[32][64];

    const int tid = threadIdx.x;
    const int e0 = (tid & 15) * 4;
    const int d0 = (tid >> 4) * 4;

    // load geometry: threads 0-127 -> k, 128-255 -> v.
    // Each matrix tile is 32 rows x 64 halves = 256 uint4 -> 2 per thread.
    const int lsel = tid >> 7;
    const int lidx = tid & 127;
    const __half* lsrc = lsel ? vbase : kbase;
    float (*ldst)[64] = lsel ? vs : ks;

    float acc[4][4];
    #pragma unroll
    for (int i = 0; i < 4; i++)
        #pragma unroll
        for (int j = 0; j < 4; j++) acc[i][j] = 0.f;
    float ksacc = 0.f;

    for (int n0 = nbeg; n0 < nend; n0 += 32) {
        #pragma unroll
        for (int it = 0; it < 2; it++) {
            int idx = lidx + 128 * it;           // 0..255
            int row = idx >> 3;                  // 0..31
            int c8 = (idx & 7) * 8;              // 0..56
            uint4 u = *(const uint4*)(lsrc + (size_t)(n0 + row) * QKVC + c8);
            const __half2* hp = (const __half2*)&u;
            #pragma unroll
            for (int i = 0; i < 4; i++) {
                float2 f = __half22float2(hp[i]);
                ldst[row][c8 + 2*i]     = f.x;
                ldst[row][c8 + 2*i + 1] = f.y;
            }
        }
        __syncthreads();
        #pragma unroll 8
        for (int nn = 0; nn < 32; nn++) {
            float kd[4], ve[4];
            *(float4*)kd = *(const float4*)&ks[nn][d0];
            *(float4*)ve = *(const float4*)&vs[nn][e0];
            #pragma unroll
            for (int i = 0; i < 4; i++)
                #pragma unroll
                for (int j = 0; j < 4; j++)
                    acc[i][j] += kd[i] * ve[j];
            if (tid < 64) ksacc += ks[nn][tid];
        }
        __syncthreads();
    }
    float* kvo = kvp + (size_t)bx * DD * DD;
    #pragma unroll
    for (int i = 0; i < 4; i++)
        #pragma unroll
        for (int j = 0; j < 4; j++)
            kvo[(d0 + i) * DD + e0 + j] = acc[i][j];
    if (tid < 64) ksump[bx * DD + tid] = ksacc;
}

__global__ __launch_bounds__(256) void kv_reduce_kernel(
    const float* __restrict__ kvp, const float* __restrict__ ksump,
    float* __restrict__ kv, float* __restrict__ ksum)
{
    const int bh = blockIdx.x;
    const int tid = threadIdx.x;
    #pragma unroll
    for (int e = 0; e < 16; e++) {
        int idx = tid + e * 256;
        float s = 0.f;
        #pragma unroll
        for (int c = 0; c < KVCHUNK; c++)
            s += kvp[(size_t)(bh * KVCHUNK + c) * DD * DD + idx];
        kv[(size_t)bh * DD * DD + idx] = s;
    }
    if (tid < DD) {
        float s = 0.f;
        #pragma unroll
        for (int c = 0; c < KVCHUNK; c++)
            s += ksump[(bh * KVCHUNK + c) * DD + tid];
        ksum[bh * DD + tid] = s;
    }
}

// out -> fp16 in [B,N,C] layout (feeds GEMM2 directly); q read as fp16
__global__ __launch_bounds__(256) void qout_kernel(
    const __half* __restrict__ qkvh, const float* __restrict__ kvmat,
    const float* __restrict__ ksum, __half* __restrict__ ah)
{
    const int bh = blockIdx.y;
    const int b = bh >> 4, h = bh & 15;
    const int n0 = blockIdx.x * 64;

    __shared__ float kvs[64][64];
    __shared__ float qs[64][64];
    __shared__ float kss[64];

    const int tid = threadIdx.x;
    const __half* qbase = qkvh + (size_t)b * NN * QKVC + h * DD;
    const float* kvb = kvmat + (size_t)bh * DD * DD;

    // kv: 64x64 floats = 1024 float4, 4 per thread
    #pragma unroll
    for (int it = 0; it < 4; it++) {
        int idx = tid + it * 256;
        int r = idx >> 4, c = (idx & 15) * 4;
        *(float4*)&kvs[r][c] = *(const float4*)(kvb + r * DD + c);
    }
    // q: 64 rows x 64 halves = 512 uint4, 2 per thread
    #pragma unroll
    for (int it = 0; it < 2; it++) {
        int idx = tid + it * 256;            // 0..511
        int r = idx >> 3;                    // 0..63
        int c8 = (idx & 7) * 8;              // 0..56
        uint4 u = *(const uint4*)(qbase + (size_t)(n0 + r) * QKVC + c8);
        const __half2* hp = (const __half2*)&u;
        #pragma unroll
        for (int i = 0; i < 4; i++) {
            float2 f = __half22float2(hp[i]);
            qs[r][c8 + 2*i]     = f.x;
            qs[r][c8 + 2*i + 1] = f.y;
        }
    }
    if (tid < 64) kss[tid] = ksum[bh * DD + tid];
    __syncthreads();

    const int r = tid >> 2;
    const int e0 = (tid & 3) * 16;

    float acc[16];
    #pragma unroll
    for (int j = 0; j < 16; j++) acc[j] = 0.f;
    float zden = 0.f;

    #pragma unroll
    for (int d = 0; d < 64; d++) {
        float qd = qs[r][d];
        zden += qd * kss[d];
        #pragma unroll
        for (int j = 0; j < 16; j++)
            acc[j] += qd * kvs[d][e0 + j];
    }
    float z = 1.f / (zden + 1e-6f);

    size_t obase = ((size_t)b * NN + n0 + r) * CC + h * DD + e0;
    __half2* oh = (__half2*)(ah + obase);
    #pragma unroll
    for (int j = 0; j < 16; j += 2)
        oh[j >> 1] = __floats2half2_rn(acc[j] * z, acc[j + 1] * z);
}

// ---------------------------------------------------------------------------
extern "C" void kernel_launch(void* const* d_in, const int* in_sizes, int n_in,
                              void* d_out, int out_size)
{
    const float* x     = (const float*)d_in[0];
    const float* Wqkv  = (const float*)d_in[1];
    const float* Wproj = (const float*)d_in[2];
    const float* bproj = (const float*)d_in[3];
    float* out = (float*)d_out;

    float *kv_p, *ksum_p, *kvp_p, *ksump_p;
    __half *qkvh, *xh, *ah, *wqh, *wql, *wph, *wpl;
    cudaGetSymbolAddress((void**)&qkvh, g_qkvh);
    cudaGetSymbolAddress((void**)&kv_p,  g_kv);
    cudaGetSymbolAddress((void**)&ksum_p, g_ksum);
    cudaGetSymbolAddress((void**)&kvp_p,  g_kvp);
    cudaGetSymbolAddress((void**)&ksump_p, g_ksump);
    cudaGetSymbolAddress((void**)&xh, g_xh);
    cudaGetSymbolAddress((void**)&ah, g_attn_h);
    cudaGetSymbolAddress((void**)&wqh, g_wqkvT_hi);
    cudaGetSymbolAddress((void**)&wql, g_wqkvT_lo);
    cudaGetSymbolAddress((void**)&wph, g_wprojT_hi);
    cudaGetSymbolAddress((void**)&wpl, g_wprojT_lo);

    cudaFuncSetAttribute(gemm_mma<true, false, true>,
                         cudaFuncAttributeMaxDynamicSharedMemorySize, GEMM_SMEM);
    cudaFuncSetAttribute(gemm_mma<false, true, false>,
                         cudaFuncAttributeMaxDynamicSharedMemorySize, GEMM_SMEM);

    // x -> fp16
    {
        size_t n2 = (size_t)MTOT * CC / 2;
        cvt_f16<<<(unsigned)((n2 + 255) / 256), 256>>>(
            (const float2*)x, (__half2*)xh, n2);
    }
    // transpose + split weights to [N][K] fp16 hi/lo
    transpose_cvt<<<dim3(QKVC / 32, KDIM / 32), 256>>>(Wqkv, wqh, wql, KDIM, QKVC);
    transpose_cvt<<<dim3(CC / 32, KDIM / 32), 256>>>(Wproj, wph, wpl, KDIM, CC);

    // GEMM1: qkv = x @ W_qkv  (fused elu+1 on cols < 2048, fp16 out)
    gemm_mma<true, false, true><<<dim3(QKVC / 128, MTOT / 256), 256, GEMM_SMEM>>>(
        xh, wqh, wql, nullptr, qkvh, QKVC);

    // attention state (8-way N-split, deterministic reduce) + output
    kv_part_kernel<<<BB * HH * KVCHUNK, 256>>>(qkvh, kvp_p, ksump_p);
    kv_reduce_kernel<<<BB * HH, 256>>>(kvp_p, ksump_p, kv_p, ksum_p);
    qout_kernel<<<dim3(NN / 64, BB * HH), 256>>>(qkvh, kv_p, ksum_p, ah);

    // GEMM2: out = attn @ W_proj + b_proj (fp32 out)
    gemm_mma<false, true, false><<<dim3(CC / 128, MTOT / 256), 256, GEMM_SMEM>>>(
        ah, wph, wpl, bproj, out, CC);
}

// round 12
// speedup vs baseline: 1.0858x; 1.0858x over previous
#include <cuda_runtime.h>
#include <cuda_fp16.h>
#include <math.h>
#include <cstdint>

#define BB 4
#define NN 4096
#define CC 1024
#define HH 16
#define DD 64
#define MTOT (BB*NN)        // 16384
#define QKVC (3*CC)         // 3072
#define KDIM 1024
#define KVCHUNK 8

// ---------------- scratch (device globals; allocation-free) ----------------
__device__ __half g_qkvh[(size_t)MTOT * QKVC];   // fp16 qkv (post-elu q,k; raw v)
__device__ __half g_xh[(size_t)MTOT * CC];
__device__ __half g_attn_h[(size_t)MTOT * CC];
__device__ __half g_wqkvT_hi[(size_t)QKVC * KDIM];
__device__ __half g_wqkvT_lo[(size_t)QKVC * KDIM];
__device__ __half g_wprojT_hi[(size_t)CC * KDIM];
__device__ __half g_wprojT_lo[(size_t)CC * KDIM];
__device__ float g_kvp[KVCHUNK * BB*HH*DD*DD];
__device__ float g_ksump[KVCHUNK * BB*HH*DD];
__device__ float g_kv[BB*HH*DD*DD];
__device__ float g_ksum[BB*HH*DD];

// ---------------- PTX helpers (baseline sm_80-class; assemble on sm_103) ----
__device__ __forceinline__ uint32_t smem_u32(const void* p) {
    uint32_t a;
    asm("{ .reg .u64 t; cvta.to.shared.u64 t, %1; cvt.u32.u64 %0, t; }" : "=r"(a) : "l"(p));
    return a;
}
__device__ __forceinline__ void cp16(uint32_t s, const void* g) {
    asm volatile("cp.async.cg.shared.global [%0], [%1], 16;" :: "r"(s), "l"(g));
}
#define CP_COMMIT() asm volatile("cp.async.commit_group;" ::: "memory")
#define CP_WAIT0()  asm volatile("cp.async.wait_group 0;" ::: "memory")

__device__ __forceinline__ void ldmx4(uint32_t* r, uint32_t addr) {
    asm volatile("ldmatrix.sync.aligned.m8n8.x4.shared.b16 {%0,%1,%2,%3}, [%4];"
                 : "=r"(r[0]), "=r"(r[1]), "=r"(r[2]), "=r"(r[3]) : "r"(addr));
}
__device__ __forceinline__ void mma16816(float* d, const uint32_t* a, const uint32_t* b) {
    asm volatile("mma.sync.aligned.m16n8k16.row.col.f32.f16.f16.f32 "
                 "{%0,%1,%2,%3}, {%4,%5,%6,%7}, {%8,%9}, {%0,%1,%2,%3};"
                 : "+f"(d[0]), "+f"(d[1]), "+f"(d[2]), "+f"(d[3])
                 : "r"(a[0]), "r"(a[1]), "r"(a[2]), "r"(a[3]), "r"(b[0]), "r"(b[1]));
}

// ---------------- converts ----------------
__global__ void cvt_f16(const float2* __restrict__ in, __half2* __restrict__ out, size_t n2) {
    size_t i = (size_t)blockIdx.x * blockDim.x + threadIdx.x;
    if (i >= n2) return;
    float2 v = in[i];
    out[i] = __floats2half2_rn(v.x, v.y);
}

// transpose + split: in [K][N] fp32 -> out hi/lo [N][K] fp16
__global__ __launch_bounds__(256) void transpose_cvt(
    const float* __restrict__ in, __half* __restrict__ hi,
    __half* __restrict__ lo, int K, int N) {
    __shared__ float t[32][33];
    int n0 = blockIdx.x * 32, k0 = blockIdx.y * 32;
    int tx = threadIdx.x & 31, ty = threadIdx.x >> 5;
    #pragma unroll
    for (int i = 0; i < 4; i++)
        t[ty + 8*i][tx] = in[(size_t)(k0 + ty + 8*i) * N + n0 + tx];
    __syncthreads();
    #pragma unroll
    for (int i = 0; i < 4; i++) {
        float v = t[tx][ty + 8*i];
        size_t o = (size_t)(n0 + ty + 8*i) * K + k0 + tx;
        __half h = __float2half_rn(v);
        hi[o] = h;
        lo[o] = __float2half_rn(v - __half2float(h));
    }
}

// ---------------- HMMA fp16 2-term GEMM: C[M,N] = A[M,K] @ (Bh+Bl)[N,K]^T ----
// Block tile 128x128, BK=64, 4 warps (2M x 2N), warp tile 64x64,
// 2-stage cp.async, 96KB smem, 2 CTAs/SM for cross-CTA bubble overlap.
#define KITERS (KDIM / 64)       // 16
#define ATB 16384u               // A: 128 rows x 128B
#define BTB 16384u               // Bh: 128 rows x 128B
#define STAGEB (ATB + 2u*BTB)    // 49152
#define GEMM_SMEM (2 * 49152)    // 98304

template<bool ELU, bool BIAS, bool OUT16>
__global__ __launch_bounds__(128, 2) void gemm_mma(
    const __half* __restrict__ A,
    const __half* __restrict__ Bhi, const __half* __restrict__ Blo,
    const float* __restrict__ bias, void* __restrict__ Cv, int N)
{
    extern __shared__ char sm[];
    const uint32_t sb = smem_u32(sm);
    const int tid = threadIdx.x;
    const int lane = tid & 31, wid = tid >> 5;
    const int wm = (wid >> 1) * 64;      // warp M offset (0,64)
    const int wn = (wid & 1) * 64;       // warp N offset (0,64)
    const int m0 = blockIdx.y * 128, n0 = blockIdx.x * 128;

    // ---- cp.async geometry: 128B rows, 8 chunks of 16B, 8-way XOR swizzle ----
    // 128 rows x 8 chunks = 1024 chunks / 128 threads = 8 per thread per tile.
    const int ch = tid & 7;
    const int rbase = tid >> 3;          // 0..15
    uint32_t so[8]; size_t gA[8], gB[8];
    #pragma unroll
    for (int i = 0; i < 8; i++) {
        int r = rbase + 16 * i;
        so[i] = (uint32_t)(r * 128) + (uint32_t)((ch ^ (r & 7)) << 4);
        gA[i] = (size_t)(m0 + r) * KDIM + ch * 8;
        gB[i] = (size_t)(n0 + r) * KDIM + ch * 8;
    }

    // ---- ldmatrix geometry ----
    int ra[4], rb[4];
    #pragma unroll
    for (int mt = 0; mt < 4; mt++) ra[mt] = wm + mt * 16 + (lane & 15);
    #pragma unroll
    for (int np = 0; np < 4; np++)
        rb[np] = wn + np * 16 + (lane & 7) + ((lane & 16) ? 8 : 0);
    const int caH = lane >> 4;
    const int cbH = (lane >> 3) & 1;

    float acc[4][8][4];
    #pragma unroll
    for (int mt = 0; mt < 4; mt++)
        #pragma unroll
        for (int nt = 0; nt < 8; nt++)
            #pragma unroll
            for (int j = 0; j < 4; j++) acc[mt][nt][j] = 0.f;

    auto issue = [&](int s) {
        uint32_t st = sb + (uint32_t)(s & 1) * STAGEB;
        size_t ko = (size_t)s * 64;
        #pragma unroll
        for (int i = 0; i < 8; i++) {
            cp16(st + so[i],            A   + gA[i] + ko);
            cp16(st + ATB + so[i],      Bhi + gB[i] + ko);
            cp16(st + ATB + BTB + so[i], Blo + gB[i] + ko);
        }
        CP_COMMIT();
    };

    issue(0);

    for (int s = 0; s < KITERS; s++) {
        CP_WAIT0();
        __syncthreads();                 // stage s ready; all warps past compute(s-1)
        if (s + 1 < KITERS) issue(s + 1);  // fills the slot freed by compute(s-1)

        const uint32_t st = sb + (uint32_t)(s & 1) * STAGEB;
        #pragma unroll
        for (int ks = 0; ks < 4; ks++) {
            uint32_t ah[4][4];
            #pragma unroll
            for (int mt = 0; mt < 4; mt++) {
                uint32_t c = (uint32_t)(ks * 2 + caH);
                uint32_t off = (uint32_t)(ra[mt] * 128) + ((c ^ (ra[mt] & 7)) << 4);
                ldmx4(ah[mt], st + off);
            }
            #pragma unroll
            for (int np = 0; np < 4; np++) {
                uint32_t c = (uint32_t)(ks * 2 + cbH);
                uint32_t off = (uint32_t)(rb[np] * 128) + ((c ^ (rb[np] & 7)) << 4);
                uint32_t bh[4], bl[4];
                ldmx4(bh, st + ATB + off);
                ldmx4(bl, st + ATB + BTB + off);
                #pragma unroll
                for (int mt = 0; mt < 4; mt++) {
                    mma16816(acc[mt][2*np  ], ah[mt], bh + 0);
                    mma16816(acc[mt][2*np  ], ah[mt], bl + 0);
                    mma16816(acc[mt][2*np+1], ah[mt], bh + 2);
                    mma16816(acc[mt][2*np+1], ah[mt], bl + 2);
                }
            }
        }
    }

    // ---- epilogue ----
    #pragma unroll
    for (int mt = 0; mt < 4; mt++) {
        #pragma unroll
        for (int nt = 0; nt < 8; nt++) {
            int row = m0 + wm + mt * 16 + (lane >> 2);
            int col = n0 + wn + nt * 8 + (lane & 3) * 2;
            #pragma unroll
            for (int half = 0; half < 2; half++) {
                int r = row + half * 8;
                float v0 = acc[mt][nt][half * 2 + 0];
                float v1 = acc[mt][nt][half * 2 + 1];
                if (ELU) {
                    if (col < 2048)     v0 = (v0 > 0.f) ? (v0 + 1.f) : expf(v0);
                    if (col + 1 < 2048) v1 = (v1 > 0.f) ? (v1 + 1.f) : expf(v1);
                }
                if (BIAS) { v0 += bias[col]; v1 += bias[col + 1]; }
                if (OUT16) {
                    __half* Ch = (__half*)Cv;
                    *(__half2*)(Ch + (size_t)r * N + col) = __floats2half2_rn(v0, v1);
                } else {
                    float* Cf = (float*)Cv;
                    float2 o; o.x = v0; o.y = v1;
                    *(float2*)(Cf + (size_t)r * N + col) = o;
                }
            }
        }
    }
}

// ---------------- attention: kv partial over N-chunk (fp16 in, fp32 accum) ----
__global__ __launch_bounds__(256) void kv_part_kernel(
    const __half* __restrict__ qkvh, float* __restrict__ kvp, float* __restrict__ ksump)
{
    const int bx = blockIdx.x;          // 0..511
    const int bh = bx >> 3, chunk = bx & 7;
    const int b = bh >> 4, h = bh & 15;
    const int nbeg = chunk * (NN / KVCHUNK), nend = nbeg + NN / KVCHUNK;
    const __half* kbase = qkvh + (size_t)b * NN * QKVC + CC + h * DD;
    const __half* vbase = qkvh + (size_t)b * NN * QKVC + 2 * CC + h * DD;

    __shared__ float ks[32][64];
    __shared__ float vs[32][64];

    const int tid = threadIdx.x;
    const int e0 = (tid & 15) * 4;
    const int d0 = (tid >> 4) * 4;

    const int lsel = tid >> 7;
    const int lidx = tid & 127;
    const __half* lsrc = lsel ? vbase : kbase;
    float (*ldst)[64] = lsel ? vs : ks;

    float acc[4][4];
    #pragma unroll
    for (int i = 0; i < 4; i++)
        #pragma unroll
        for (int j = 0; j < 4; j++) acc[i][j] = 0.f;
    float ksacc = 0.f;

    for (int n0 = nbeg; n0 < nend; n0 += 32) {
        #pragma unroll
        for (int it = 0; it < 2; it++) {
            int idx = lidx + 128 * it;           // 0..255
            int row = idx >> 3;                  // 0..31
            int c8 = (idx & 7) * 8;              // 0..56
            uint4 u = *(const uint4*)(lsrc + (size_t)(n0 + row) * QKVC + c8);
            const __half2* hp = (const __half2*)&u;
            #pragma unroll
            for (int i = 0; i < 4; i++) {
                float2 f = __half22float2(hp[i]);
                ldst[row][c8 + 2*i]     = f.x;
                ldst[row][c8 + 2*i + 1] = f.y;
            }
        }
        __syncthreads();
        #pragma unroll 8
        for (int nn = 0; nn < 32; nn++) {
            float kd[4], ve[4];
            *(float4*)kd = *(const float4*)&ks[nn][d0];
            *(float4*)ve = *(const float4*)&vs[nn][e0];
            #pragma unroll
            for (int i = 0; i < 4; i++)
                #pragma unroll
                for (int j = 0; j < 4; j++)
                    acc[i][j] += kd[i] * ve[j];
            if (tid < 64) ksacc += ks[nn][tid];
        }
        __syncthreads();
    }
    float* kvo = kvp + (size_t)bx * DD * DD;
    #pragma unroll
    for (int i = 0; i < 4; i++)
        #pragma unroll
        for (int j = 0; j < 4; j++)
            kvo[(d0 + i) * DD + e0 + j] = acc[i][j];
    if (tid < 64) ksump[bx * DD + tid] = ksacc;
}

__global__ __launch_bounds__(256) void kv_reduce_kernel(
    const float* __restrict__ kvp, const float* __restrict__ ksump,
    float* __restrict__ kv, float* __restrict__ ksum)
{
    const int bh = blockIdx.x;
    const int tid = threadIdx.x;
    #pragma unroll
    for (int e = 0; e < 16; e++) {
        int idx = tid + e * 256;
        float s = 0.f;
        #pragma unroll
        for (int c = 0; c < KVCHUNK; c++)
            s += kvp[(size_t)(bh * KVCHUNK + c) * DD * DD + idx];
        kv[(size_t)bh * DD * DD + idx] = s;
    }
    if (tid < DD) {
        float s = 0.f;
        #pragma unroll
        for (int c = 0; c < KVCHUNK; c++)
            s += ksump[(bh * KVCHUNK + c) * DD + tid];
        ksum[bh * DD + tid] = s;
    }
}

// out -> fp16 in [B,N,C] layout (feeds GEMM2 directly); q read as fp16
__global__ __launch_bounds__(256) void qout_kernel(
    const __half* __restrict__ qkvh, const float* __restrict__ kvmat,
    const float* __restrict__ ksum, __half* __restrict__ ah)
{
    const int bh = blockIdx.y;
    const int b = bh >> 4, h = bh & 15;
    const int n0 = blockIdx.x * 64;

    __shared__ float kvs[64][64];
    __shared__ float qs[64][64];
    __shared__ float kss[64];

    const int tid = threadIdx.x;
    const __half* qbase = qkvh + (size_t)b * NN * QKVC + h * DD;
    const float* kvb = kvmat + (size_t)bh * DD * DD;

    #pragma unroll
    for (int it = 0; it < 4; it++) {
        int idx = tid + it * 256;
        int r = idx >> 4, c = (idx & 15) * 4;
        *(float4*)&kvs[r][c] = *(const float4*)(kvb + r * DD + c);
    }
    #pragma unroll
    for (int it = 0; it < 2; it++) {
        int idx = tid + it * 256;            // 0..511
        int r = idx >> 3;                    // 0..63
        int c8 = (idx & 7) * 8;              // 0..56
        uint4 u = *(const uint4*)(qbase + (size_t)(n0 + r) * QKVC + c8);
        const __half2* hp = (const __half2*)&u;
        #pragma unroll
        for (int i = 0; i < 4; i++) {
            float2 f = __half22float2(hp[i]);
            qs[r][c8 + 2*i]     = f.x;
            qs[r][c8 + 2*i + 1] = f.y;
        }
    }
    if (tid < 64) kss[tid] = ksum[bh * DD + tid];
    __syncthreads();

    const int r = tid >> 2;
    const int e0 = (tid & 3) * 16;

    float acc[16];
    #pragma unroll
    for (int j = 0; j < 16; j++) acc[j] = 0.f;
    float zden = 0.f;

    #pragma unroll
    for (int d = 0; d < 64; d++) {
        float qd = qs[r][d];
        zden += qd * kss[d];
        #pragma unroll
        for (int j = 0; j < 16; j++)
            acc[j] += qd * kvs[d][e0 + j];
    }
    float z = 1.f / (zden + 1e-6f);

    size_t obase = ((size_t)b * NN + n0 + r) * CC + h * DD + e0;
    __half2* oh = (__half2*)(ah + obase);
    #pragma unroll
    for (int j = 0; j < 16; j += 2)
        oh[j >> 1] = __floats2half2_rn(acc[j] * z, acc[j + 1] * z);
}

// ---------------------------------------------------------------------------
extern "C" void kernel_launch(void* const* d_in, const int* in_sizes, int n_in,
                              void* d_out, int out_size)
{
    const float* x     = (const float*)d_in[0];
    const float* Wqkv  = (const float*)d_in[1];
    const float* Wproj = (const float*)d_in[2];
    const float* bproj = (const float*)d_in[3];
    float* out = (float*)d_out;

    float *kv_p, *ksum_p, *kvp_p, *ksump_p;
    __half *qkvh, *xh, *ah, *wqh, *wql, *wph, *wpl;
    cudaGetSymbolAddress((void**)&qkvh, g_qkvh);
    cudaGetSymbolAddress((void**)&kv_p,  g_kv);
    cudaGetSymbolAddress((void**)&ksum_p, g_ksum);
    cudaGetSymbolAddress((void**)&kvp_p,  g_kvp);
    cudaGetSymbolAddress((void**)&ksump_p, g_ksump);
    cudaGetSymbolAddress((void**)&xh, g_xh);
    cudaGetSymbolAddress((void**)&ah, g_attn_h);
    cudaGetSymbolAddress((void**)&wqh, g_wqkvT_hi);
    cudaGetSymbolAddress((void**)&wql, g_wqkvT_lo);
    cudaGetSymbolAddress((void**)&wph, g_wprojT_hi);
    cudaGetSymbolAddress((void**)&wpl, g_wprojT_lo);

    cudaFuncSetAttribute(gemm_mma<true, false, true>,
                         cudaFuncAttributeMaxDynamicSharedMemorySize, GEMM_SMEM);
    cudaFuncSetAttribute(gemm_mma<false, true, false>,
                         cudaFuncAttributeMaxDynamicSharedMemorySize, GEMM_SMEM);

    // x -> fp16
    {
        size_t n2 = (size_t)MTOT * CC / 2;
        cvt_f16<<<(unsigned)((n2 + 255) / 256), 256>>>(
            (const float2*)x, (__half2*)xh, n2);
    }
    // transpose + split weights to [N][K] fp16 hi/lo
    transpose_cvt<<<dim3(QKVC / 32, KDIM / 32), 256>>>(Wqkv, wqh, wql, KDIM, QKVC);
    transpose_cvt<<<dim3(CC / 32, KDIM / 32), 256>>>(Wproj, wph, wpl, KDIM, CC);

    // GEMM1: qkv = x @ W_qkv  (fused elu+1 on cols < 2048, fp16 out)
    gemm_mma<true, false, true><<<dim3(QKVC / 128, MTOT / 128), 128, GEMM_SMEM>>>(
        xh, wqh, wql, nullptr, qkvh, QKVC);

    // attention state (8-way N-split, deterministic reduce) + output
    kv_part_kernel<<<BB * HH * KVCHUNK, 256>>>(qkvh, kvp_p, ksump_p);
    kv_reduce_kernel<<<BB * HH, 256>>>(kvp_p, ksump_p, kv_p, ksum_p);
    qout_kernel<<<dim3(NN / 64, BB * HH), 256>>>(qkvh, kv_p, ksum_p, ah);

    // GEMM2: out = attn @ W_proj + b_proj (fp32 out)
    gemm_mma<false, true, false><<<dim3(CC / 128, MTOT / 128), 128, GEMM_SMEM>>>(
        ah, wph, wpl, bproj, out, CC);
}

// round 13
// speedup vs baseline: 1.4130x; 1.3013x over previous
#include <cuda_runtime.h>
#include <cuda_fp16.h>
#include <math.h>
#include <cstdint>

#define BB 4
#define NN 4096
#define CC 1024
#define HH 16
#define DD 64
#define MTOT (BB*NN)        // 16384
#define QKVC (3*CC)         // 3072
#define KDIM 1024
#define KVCHUNK 8

// ---------------- scratch (device globals; allocation-free) ----------------
__device__ __half g_qkvh[(size_t)MTOT * QKVC];   // fp16 qkv (post-elu q,k; raw v)
__device__ __half g_xh[(size_t)MTOT * CC];
__device__ __half g_attn_h[(size_t)MTOT * CC];
__device__ __half g_wqkvT[(size_t)QKVC * KDIM];  // [3072][1024] fp16, N-major
__device__ __half g_wprojT[(size_t)CC * KDIM];   // [1024][1024]
__device__ float g_kvp[KVCHUNK * BB*HH*DD*DD];
__device__ float g_ksump[KVCHUNK * BB*HH*DD];
__device__ float g_kv[BB*HH*DD*DD];
__device__ float g_ksum[BB*HH*DD];

// ---------------- PTX helpers (baseline sm_80-class; assemble on sm_103) ----
__device__ __forceinline__ uint32_t smem_u32(const void* p) {
    uint32_t a;
    asm("{ .reg .u64 t; cvta.to.shared.u64 t, %1; cvt.u32.u64 %0, t; }" : "=r"(a) : "l"(p));
    return a;
}
__device__ __forceinline__ void cp16(uint32_t s, const void* g) {
    asm volatile("cp.async.cg.shared.global [%0], [%1], 16;" :: "r"(s), "l"(g));
}
#define CP_COMMIT() asm volatile("cp.async.commit_group;" ::: "memory")
#define CP_WAIT1()  asm volatile("cp.async.wait_group 1;" ::: "memory")

__device__ __forceinline__ void ldmx4(uint32_t* r, uint32_t addr) {
    asm volatile("ldmatrix.sync.aligned.m8n8.x4.shared.b16 {%0,%1,%2,%3}, [%4];"
                 : "=r"(r[0]), "=r"(r[1]), "=r"(r[2]), "=r"(r[3]) : "r"(addr));
}
__device__ __forceinline__ void mma16816(float* d, const uint32_t* a, const uint32_t* b) {
    asm volatile("mma.sync.aligned.m16n8k16.row.col.f32.f16.f16.f32 "
                 "{%0,%1,%2,%3}, {%4,%5,%6,%7}, {%8,%9}, {%0,%1,%2,%3};"
                 : "+f"(d[0]), "+f"(d[1]), "+f"(d[2]), "+f"(d[3])
                 : "r"(a[0]), "r"(a[1]), "r"(a[2]), "r"(a[3]), "r"(b[0]), "r"(b[1]));
}

// ---------------- converts ----------------
__global__ void cvt_f16(const float2* __restrict__ in, __half2* __restrict__ out, size_t n2) {
    size_t i = (size_t)blockIdx.x * blockDim.x + threadIdx.x;
    if (i >= n2) return;
    float2 v = in[i];
    out[i] = __floats2half2_rn(v.x, v.y);
}

// transpose: in [K][N] fp32 -> out [N][K] fp16
__global__ __launch_bounds__(256) void transpose_cvt(
    const float* __restrict__ in, __half* __restrict__ outp, int K, int N) {
    __shared__ float t[32][33];
    int n0 = blockIdx.x * 32, k0 = blockIdx.y * 32;
    int tx = threadIdx.x & 31, ty = threadIdx.x >> 5;
    #pragma unroll
    for (int i = 0; i < 4; i++)
        t[ty + 8*i][tx] = in[(size_t)(k0 + ty + 8*i) * N + n0 + tx];
    __syncthreads();
    #pragma unroll
    for (int i = 0; i < 4; i++) {
        float v = t[tx][ty + 8*i];
        size_t o = (size_t)(n0 + ty + 8*i) * K + k0 + tx;
        outp[o] = __float2half_rn(v);
    }
}

// ---------------- HMMA fp16 GEMM: C[M,N] = A[M,K] @ B[N,K]^T ----------------
// Block tile 128x128, BK=64, 4 warps (2M x 2N), warp tile 64x64,
// 3-stage cp.async, 96KB smem, 2 CTAs/SM.
#define KITERS (KDIM / 64)       // 16
#define ATB 16384u               // A: 128 rows x 128B
#define BTB 16384u               // B: 128 rows x 128B
#define STAGEB (ATB + BTB)       // 32768
#define GEMM_SMEM (3 * 32768)    // 98304

template<bool ELU, bool BIAS, bool OUT16>
__global__ __launch_bounds__(128, 2) void gemm_mma(
    const __half* __restrict__ A, const __half* __restrict__ B,
    const float* __restrict__ bias, void* __restrict__ Cv, int N)
{
    extern __shared__ char sm[];
    const uint32_t sb = smem_u32(sm);
    const int tid = threadIdx.x;
    const int lane = tid & 31, wid = tid >> 5;
    const int wm = (wid >> 1) * 64;      // warp M offset (0,64)
    const int wn = (wid & 1) * 64;       // warp N offset (0,64)
    const int m0 = blockIdx.y * 128, n0 = blockIdx.x * 128;

    // ---- cp.async geometry: 128B rows, 8 chunks of 16B, 8-way XOR swizzle ----
    const int ch = tid & 7;
    const int rbase = tid >> 3;          // 0..15
    uint32_t so[8]; size_t gA[8], gB[8];
    #pragma unroll
    for (int i = 0; i < 8; i++) {
        int r = rbase + 16 * i;
        so[i] = (uint32_t)(r * 128) + (uint32_t)((ch ^ (r & 7)) << 4);
        gA[i] = (size_t)(m0 + r) * KDIM + ch * 8;
        gB[i] = (size_t)(n0 + r) * KDIM + ch * 8;
    }

    // ---- ldmatrix geometry ----
    int ra[4], rb[4];
    #pragma unroll
    for (int mt = 0; mt < 4; mt++) ra[mt] = wm + mt * 16 + (lane & 15);
    #pragma unroll
    for (int np = 0; np < 4; np++)
        rb[np] = wn + np * 16 + (lane & 7) + ((lane & 16) ? 8 : 0);
    const int caH = lane >> 4;
    const int cbH = (lane >> 3) & 1;

    float acc[4][8][4];
    #pragma unroll
    for (int mt = 0; mt < 4; mt++)
        #pragma unroll
        for (int nt = 0; nt < 8; nt++)
            #pragma unroll
            for (int j = 0; j < 4; j++) acc[mt][nt][j] = 0.f;

    auto issue = [&](int s) {
        if (s < KITERS) {
            uint32_t st = sb + (uint32_t)(s % 3) * STAGEB;
            size_t ko = (size_t)s * 64;
            #pragma unroll
            for (int i = 0; i < 8; i++) {
                cp16(st + so[i],       A + gA[i] + ko);
                cp16(st + ATB + so[i], B + gB[i] + ko);
            }
        }
        CP_COMMIT();
    };

    issue(0);
    issue(1);

    for (int s = 0; s < KITERS; s++) {
        CP_WAIT1();          // stage s landed (s+1 may be in flight)
        __syncthreads();     // all warps past compute(s-1) -> slot (s+2)%3 free
        issue(s + 2);

        const uint32_t st = sb + (uint32_t)(s % 3) * STAGEB;
        #pragma unroll
        for (int ks = 0; ks < 4; ks++) {
            uint32_t ah[4][4];
            #pragma unroll
            for (int mt = 0; mt < 4; mt++) {
                uint32_t c = (uint32_t)(ks * 2 + caH);
                uint32_t off = (uint32_t)(ra[mt] * 128) + ((c ^ (ra[mt] & 7)) << 4);
                ldmx4(ah[mt], st + off);
            }
            #pragma unroll
            for (int np = 0; np < 4; np++) {
                uint32_t c = (uint32_t)(ks * 2 + cbH);
                uint32_t off = (uint32_t)(rb[np] * 128) + ((c ^ (rb[np] & 7)) << 4);
                uint32_t bh[4];
                ldmx4(bh, st + ATB + off);
                #pragma unroll
                for (int mt = 0; mt < 4; mt++) {
                    mma16816(acc[mt][2*np  ], ah[mt], bh + 0);
                    mma16816(acc[mt][2*np+1], ah[mt], bh + 2);
                }
            }
        }
    }

    // ---- epilogue ----
    #pragma unroll
    for (int mt = 0; mt < 4; mt++) {
        #pragma unroll
        for (int nt = 0; nt < 8; nt++) {
            int row = m0 + wm + mt * 16 + (lane >> 2);
            int col = n0 + wn + nt * 8 + (lane & 3) * 2;
            #pragma unroll
            for (int half = 0; half < 2; half++) {
                int r = row + half * 8;
                float v0 = acc[mt][nt][half * 2 + 0];
                float v1 = acc[mt][nt][half * 2 + 1];
                if (ELU) {
                    if (col < 2048)     v0 = (v0 > 0.f) ? (v0 + 1.f) : expf(v0);
                    if (col + 1 < 2048) v1 = (v1 > 0.f) ? (v1 + 1.f) : expf(v1);
                }
                if (BIAS) { v0 += bias[col]; v1 += bias[col + 1]; }
                if (OUT16) {
                    __half* Ch = (__half*)Cv;
                    *(__half2*)(Ch + (size_t)r * N + col) = __floats2half2_rn(v0, v1);
                } else {
                    float* Cf = (float*)Cv;
                    float2 o; o.x = v0; o.y = v1;
                    *(float2*)(Cf + (size_t)r * N + col) = o;
                }
            }
        }
    }
}

// ---------------- attention: kv partial over N-chunk (fp16 in, fp32 accum) ----
__global__ __launch_bounds__(256) void kv_part_kernel(
    const __half* __restrict__ qkvh, float* __restrict__ kvp, float* __restrict__ ksump)
{
    const int bx = blockIdx.x;          // 0..511
    const int bh = bx >> 3, chunk = bx & 7;
    const int b = bh >> 4, h = bh & 15;
    const int nbeg = chunk * (NN / KVCHUNK), nend = nbeg + NN / KVCHUNK;
    const __half* kbase = qkvh + (size_t)b * NN * QKVC + CC + h * DD;
    const __half* vbase = qkvh + (size_t)b * NN * QKVC + 2 * CC + h * DD;

    __shared__ float ks[32][64];
    __shared__ float vs[32][64];

    const int tid = threadIdx.x;
    const int e0 = (tid & 15) * 4;
    const int d0 = (tid >> 4) * 4;

    const int lsel = tid >> 7;
    const int lidx = tid & 127;
    const __half* lsrc = lsel ? vbase : kbase;
    float (*ldst)[64] = lsel ? vs : ks;

    float acc[4][4];
    #pragma unroll
    for (int i = 0; i < 4; i++)
        #pragma unroll
        for (int j = 0; j < 4; j++) acc[i][j] = 0.f;
    float ksacc = 0.f;

    for (int n0 = nbeg; n0 < nend; n0 += 32) {
        #pragma unroll
        for (int it = 0; it < 2; it++) {
            int idx = lidx + 128 * it;           // 0..255
            int row = idx >> 3;                  // 0..31
            int c8 = (idx & 7) * 8;              // 0..56
            uint4 u = *(const uint4*)(lsrc + (size_t)(n0 + row) * QKVC + c8);
            const __half2* hp = (const __half2*)&u;
            #pragma unroll
            for (int i = 0; i < 4; i++) {
                float2 f = __half22float2(hp[i]);
                ldst[row][c8 + 2*i]     = f.x;
                ldst[row][c8 + 2*i + 1] = f.y;
            }
        }
        __syncthreads();
        #pragma unroll 8
        for (int nn = 0; nn < 32; nn++) {
            float kd[4], ve[4];
            *(float4*)kd = *(const float4*)&ks[nn][d0];
            *(float4*)ve = *(const float4*)&vs[nn][e0];
            #pragma unroll
            for (int i = 0; i < 4; i++)
                #pragma unroll
                for (int j = 0; j < 4; j++)
                    acc[i][j] += kd[i] * ve[j];
            if (tid < 64) ksacc += ks[nn][tid];
        }
        __syncthreads();
    }
    float* kvo = kvp + (size_t)bx * DD * DD;
    #pragma unroll
    for (int i = 0; i < 4; i++)
        #pragma unroll
        for (int j = 0; j < 4; j++)
            kvo[(d0 + i) * DD + e0 + j] = acc[i][j];
    if (tid < 64) ksump[bx * DD + tid] = ksacc;
}

__global__ __launch_bounds__(256) void kv_reduce_kernel(
    const float* __restrict__ kvp, const float* __restrict__ ksump,
    float* __restrict__ kv, float* __restrict__ ksum)
{
    const int bh = blockIdx.x;
    const int tid = threadIdx.x;
    #pragma unroll
    for (int e = 0; e < 16; e++) {
        int idx = tid + e * 256;
        float s = 0.f;
        #pragma unroll
        for (int c = 0; c < KVCHUNK; c++)
            s += kvp[(size_t)(bh * KVCHUNK + c) * DD * DD + idx];
        kv[(size_t)bh * DD * DD + idx] = s;
    }
    if (tid < DD) {
        float s = 0.f;
        #pragma unroll
        for (int c = 0; c < KVCHUNK; c++)
            s += ksump[(bh * KVCHUNK + c) * DD + tid];
        ksum[bh * DD + tid] = s;
    }
}

// out -> fp16 in [B,N,C] layout (feeds GEMM2 directly); q read as fp16
__global__ __launch_bounds__(256) void qout_kernel(
    const __half* __restrict__ qkvh, const float* __restrict__ kvmat,
    const float* __restrict__ ksum, __half* __restrict__ ah)
{
    const int bh = blockIdx.y;
    const int b = bh >> 4, h = bh & 15;
    const int n0 = blockIdx.x * 64;

    __shared__ float kvs[64][64];
    __shared__ float qs[64][64];
    __shared__ float kss[64];

    const int tid = threadIdx.x;
    const __half* qbase = qkvh + (size_t)b * NN * QKVC + h * DD;
    const float* kvb = kvmat + (size_t)bh * DD * DD;

    #pragma unroll
    for (int it = 0; it < 4; it++) {
        int idx = tid + it * 256;
        int r = idx >> 4, c = (idx & 15) * 4;
        *(float4*)&kvs[r][c] = *(const float4*)(kvb + r * DD + c);
    }
    #pragma unroll
    for (int it = 0; it < 2; it++) {
        int idx = tid + it * 256;            // 0..511
        int r = idx >> 3;                    // 0..63
        int c8 = (idx & 7) * 8;              // 0..56
        uint4 u = *(const uint4*)(qbase + (size_t)(n0 + r) * QKVC + c8);
        const __half2* hp = (const __half2*)&u;
        #pragma unroll
        for (int i = 0; i < 4; i++) {
            float2 f = __half22float2(hp[i]);
            qs[r][c8 + 2*i]     = f.x;
            qs[r][c8 + 2*i + 1] = f.y;
        }
    }
    if (tid < 64) kss[tid] = ksum[bh * DD + tid];
    __syncthreads();

    const int r = tid >> 2;
    const int e0 = (tid & 3) * 16;

    float acc[16];
    #pragma unroll
    for (int j = 0; j < 16; j++) acc[j] = 0.f;
    float zden = 0.f;

    #pragma unroll
    for (int d = 0; d < 64; d++) {
        float qd = qs[r][d];
        zden += qd * kss[d];
        #pragma unroll
        for (int j = 0; j < 16; j++)
            acc[j] += qd * kvs[d][e0 + j];
    }
    float z = 1.f / (zden + 1e-6f);

    size_t obase = ((size_t)b * NN + n0 + r) * CC + h * DD + e0;
    __half2* oh = (__half2*)(ah + obase);
    #pragma unroll
    for (int j = 0; j < 16; j += 2)
        oh[j >> 1] = __floats2half2_rn(acc[j] * z, acc[j + 1] * z);
}

// ---------------------------------------------------------------------------
extern "C" void kernel_launch(void* const* d_in, const int* in_sizes, int n_in,
                              void* d_out, int out_size)
{
    const float* x     = (const float*)d_in[0];
    const float* Wqkv  = (const float*)d_in[1];
    const float* Wproj = (const float*)d_in[2];
    const float* bproj = (const float*)d_in[3];
    float* out = (float*)d_out;

    float *kv_p, *ksum_p, *kvp_p, *ksump_p;
    __half *qkvh, *xh, *ah, *wq, *wp;
    cudaGetSymbolAddress((void**)&qkvh, g_qkvh);
    cudaGetSymbolAddress((void**)&kv_p,  g_kv);
    cudaGetSymbolAddress((void**)&ksum_p, g_ksum);
    cudaGetSymbolAddress((void**)&kvp_p,  g_kvp);
    cudaGetSymbolAddress((void**)&ksump_p, g_ksump);
    cudaGetSymbolAddress((void**)&xh, g_xh);
    cudaGetSymbolAddress((void**)&ah, g_attn_h);
    cudaGetSymbolAddress((void**)&wq, g_wqkvT);
    cudaGetSymbolAddress((void**)&wp, g_wprojT);

    cudaFuncSetAttribute(gemm_mma<true, false, true>,
                         cudaFuncAttributeMaxDynamicSharedMemorySize, GEMM_SMEM);
    cudaFuncSetAttribute(gemm_mma<false, true, false>,
                         cudaFuncAttributeMaxDynamicSharedMemorySize, GEMM_SMEM);

    // x -> fp16
    {
        size_t n2 = (size_t)MTOT * CC / 2;
        cvt_f16<<<(unsigned)((n2 + 255) / 256), 256>>>(
            (const float2*)x, (__half2*)xh, n2);
    }
    // transpose weights to [N][K] fp16
    transpose_cvt<<<dim3(QKVC / 32, KDIM / 32), 256>>>(Wqkv, wq, KDIM, QKVC);
    transpose_cvt<<<dim3(CC / 32, KDIM / 32), 256>>>(Wproj, wp, KDIM, CC);

    // GEMM1: qkv = x @ W_qkv  (fused elu+1 on cols < 2048, fp16 out)
    gemm_mma<true, false, true><<<dim3(QKVC / 128, MTOT / 128), 128, GEMM_SMEM>>>(
        xh, wq, nullptr, qkvh, QKVC);

    // attention state (8-way N-split, deterministic reduce) + output
    kv_part_kernel<<<BB * HH * KVCHUNK, 256>>>(qkvh, kvp_p, ksump_p);
    kv_reduce_kernel<<<BB * HH, 256>>>(kvp_p, ksump_p, kv_p, ksum_p);
    qout_kernel<<<dim3(NN / 64, BB * HH), 256>>>(qkvh, kv_p, ksum_p, ah);

    // GEMM2: out = attn @ W_proj + b_proj (fp32 out)
    gemm_mma<false, true, false><<<dim3(CC / 128, MTOT / 128), 128, GEMM_SMEM>>>(
        ah, wp, bproj, out, CC);
}

// round 14
// speedup vs baseline: 2.3382x; 1.6548x over previous
#include <cuda_runtime.h>
#include <cuda_fp16.h>
#include <math.h>
#include <cstdint>

#define BB 4
#define NN 4096
#define CC 1024
#define HH 16
#define DD 64
#define MTOT (BB*NN)        // 16384
#define QKVC (3*CC)         // 3072
#define KDIM 1024
#define KVCHUNK 8

// ---------------- scratch (device globals; allocation-free) ----------------
__device__ __half g_qkvh[(size_t)MTOT * QKVC];   // fp16 qkv (post-elu q,k; raw v)
__device__ __half g_xh[(size_t)MTOT * CC];
__device__ __half g_attn_h[(size_t)MTOT * CC];
__device__ __half g_wqkvT[(size_t)QKVC * KDIM];  // [3072][1024] fp16, N-major
__device__ __half g_wprojT[(size_t)CC * KDIM];   // [1024][1024]
__device__ float g_kvp[KVCHUNK * BB*HH*DD*DD];
__device__ float g_ksump[KVCHUNK * BB*HH*DD];
__device__ __half g_kvh[BB*HH*DD*DD];            // reduced state hi
__device__ __half g_kvl[BB*HH*DD*DD];            // reduced state lo
__device__ float g_ksum[BB*HH*DD];

// ---------------- PTX helpers (baseline sm_80-class; assemble on sm_103) ----
__device__ __forceinline__ uint32_t smem_u32(const void* p) {
    uint32_t a;
    asm("{ .reg .u64 t; cvta.to.shared.u64 t, %1; cvt.u32.u64 %0, t; }" : "=r"(a) : "l"(p));
    return a;
}
__device__ __forceinline__ void cp16(uint32_t s, const void* g) {
    asm volatile("cp.async.cg.shared.global [%0], [%1], 16;" :: "r"(s), "l"(g));
}
#define CP_COMMIT() asm volatile("cp.async.commit_group;" ::: "memory")
#define CP_WAIT0()  asm volatile("cp.async.wait_group 0;" ::: "memory")
#define CP_WAIT1()  asm volatile("cp.async.wait_group 1;" ::: "memory")

__device__ __forceinline__ void ldmx4(uint32_t* r, uint32_t addr) {
    asm volatile("ldmatrix.sync.aligned.m8n8.x4.shared.b16 {%0,%1,%2,%3}, [%4];"
                 : "=r"(r[0]), "=r"(r[1]), "=r"(r[2]), "=r"(r[3]) : "r"(addr));
}
__device__ __forceinline__ void ldmx4t(uint32_t* r, uint32_t addr) {
    asm volatile("ldmatrix.sync.aligned.m8n8.x4.trans.shared.b16 {%0,%1,%2,%3}, [%4];"
                 : "=r"(r[0]), "=r"(r[1]), "=r"(r[2]), "=r"(r[3]) : "r"(addr));
}
__device__ __forceinline__ void mma16816(float* d, const uint32_t* a, const uint32_t* b) {
    asm volatile("mma.sync.aligned.m16n8k16.row.col.f32.f16.f16.f32 "
                 "{%0,%1,%2,%3}, {%4,%5,%6,%7}, {%8,%9}, {%0,%1,%2,%3};"
                 : "+f"(d[0]), "+f"(d[1]), "+f"(d[2]), "+f"(d[3])
                 : "r"(a[0]), "r"(a[1]), "r"(a[2]), "r"(a[3]), "r"(b[0]), "r"(b[1]));
}

// ---------------- converts ----------------
__global__ void cvt_f16(const float2* __restrict__ in, __half2* __restrict__ out, size_t n2) {
    size_t i = (size_t)blockIdx.x * blockDim.x + threadIdx.x;
    if (i >= n2) return;
    float2 v = in[i];
    out[i] = __floats2half2_rn(v.x, v.y);
}

// transpose: in [K][N] fp32 -> out [N][K] fp16
__global__ __launch_bounds__(256) void transpose_cvt(
    const float* __restrict__ in, __half* __restrict__ outp, int K, int N) {
    __shared__ float t[32][33];
    int n0 = blockIdx.x * 32, k0 = blockIdx.y * 32;
    int tx = threadIdx.x & 31, ty = threadIdx.x >> 5;
    #pragma unroll
    for (int i = 0; i < 4; i++)
        t[ty + 8*i][tx] = in[(size_t)(k0 + ty + 8*i) * N + n0 + tx];
    __syncthreads();
    #pragma unroll
    for (int i = 0; i < 4; i++) {
        float v = t[tx][ty + 8*i];
        size_t o = (size_t)(n0 + ty + 8*i) * K + k0 + tx;
        outp[o] = __float2half_rn(v);
    }
}

// ---------------- HMMA fp16 GEMM: C[M,N] = A[M,K] @ B[N,K]^T ----------------
// Block tile 128x128, BK=64, 4 warps (2M x 2N), warp tile 64x64,
// 3-stage cp.async, 96KB smem, 2 CTAs/SM.
#define KITERS (KDIM / 64)       // 16
#define ATB 16384u               // A: 128 rows x 128B
#define BTB 16384u               // B: 128 rows x 128B
#define STAGEB (ATB + BTB)       // 32768
#define GEMM_SMEM (3 * 32768)    // 98304

template<bool ELU, bool BIAS, bool OUT16>
__global__ __launch_bounds__(128, 2) void gemm_mma(
    const __half* __restrict__ A, const __half* __restrict__ B,
    const float* __restrict__ bias, void* __restrict__ Cv, int N)
{
    extern __shared__ char sm[];
    const uint32_t sb = smem_u32(sm);
    const int tid = threadIdx.x;
    const int lane = tid & 31, wid = tid >> 5;
    const int wm = (wid >> 1) * 64;
    const int wn = (wid & 1) * 64;
    const int m0 = blockIdx.y * 128, n0 = blockIdx.x * 128;

    const int ch = tid & 7;
    const int rbase = tid >> 3;          // 0..15
    uint32_t so[8]; size_t gA[8], gB[8];
    #pragma unroll
    for (int i = 0; i < 8; i++) {
        int r = rbase + 16 * i;
        so[i] = (uint32_t)(r * 128) + (uint32_t)((ch ^ (r & 7)) << 4);
        gA[i] = (size_t)(m0 + r) * KDIM + ch * 8;
        gB[i] = (size_t)(n0 + r) * KDIM + ch * 8;
    }

    int ra[4], rb[4];
    #pragma unroll
    for (int mt = 0; mt < 4; mt++) ra[mt] = wm + mt * 16 + (lane & 15);
    #pragma unroll
    for (int np = 0; np < 4; np++)
        rb[np] = wn + np * 16 + (lane & 7) + ((lane & 16) ? 8 : 0);
    const int caH = lane >> 4;
    const int cbH = (lane >> 3) & 1;

    float acc[4][8][4];
    #pragma unroll
    for (int mt = 0; mt < 4; mt++)
        #pragma unroll
        for (int nt = 0; nt < 8; nt++)
            #pragma unroll
            for (int j = 0; j < 4; j++) acc[mt][nt][j] = 0.f;

    auto issue = [&](int s) {
        if (s < KITERS) {
            uint32_t st = sb + (uint32_t)(s % 3) * STAGEB;
            size_t ko = (size_t)s * 64;
            #pragma unroll
            for (int i = 0; i < 8; i++) {
                cp16(st + so[i],       A + gA[i] + ko);
                cp16(st + ATB + so[i], B + gB[i] + ko);
            }
        }
        CP_COMMIT();
    };

    issue(0);
    issue(1);

    for (int s = 0; s < KITERS; s++) {
        CP_WAIT1();
        __syncthreads();
        issue(s + 2);

        const uint32_t st = sb + (uint32_t)(s % 3) * STAGEB;
        #pragma unroll
        for (int ks = 0; ks < 4; ks++) {
            uint32_t ah[4][4];
            #pragma unroll
            for (int mt = 0; mt < 4; mt++) {
                uint32_t c = (uint32_t)(ks * 2 + caH);
                uint32_t off = (uint32_t)(ra[mt] * 128) + ((c ^ (ra[mt] & 7)) << 4);
                ldmx4(ah[mt], st + off);
            }
            #pragma unroll
            for (int np = 0; np < 4; np++) {
                uint32_t c = (uint32_t)(ks * 2 + cbH);
                uint32_t off = (uint32_t)(rb[np] * 128) + ((c ^ (rb[np] & 7)) << 4);
                uint32_t bh[4];
                ldmx4(bh, st + ATB + off);
                #pragma unroll
                for (int mt = 0; mt < 4; mt++) {
                    mma16816(acc[mt][2*np  ], ah[mt], bh + 0);
                    mma16816(acc[mt][2*np+1], ah[mt], bh + 2);
                }
            }
        }
    }

    #pragma unroll
    for (int mt = 0; mt < 4; mt++) {
        #pragma unroll
        for (int nt = 0; nt < 8; nt++) {
            int row = m0 + wm + mt * 16 + (lane >> 2);
            int col = n0 + wn + nt * 8 + (lane & 3) * 2;
            #pragma unroll
            for (int half = 0; half < 2; half++) {
                int r = row + half * 8;
                float v0 = acc[mt][nt][half * 2 + 0];
                float v1 = acc[mt][nt][half * 2 + 1];
                if (ELU) {
                    if (col < 2048)     v0 = (v0 > 0.f) ? (v0 + 1.f) : expf(v0);
                    if (col + 1 < 2048) v1 = (v1 > 0.f) ? (v1 + 1.f) : expf(v1);
                }
                if (BIAS) { v0 += bias[col]; v1 += bias[col + 1]; }
                if (OUT16) {
                    __half* Ch = (__half*)Cv;
                    *(__half2*)(Ch + (size_t)r * N + col) = __floats2half2_rn(v0, v1);
                } else {
                    float* Cf = (float*)Cv;
                    float2 o; o.x = v0; o.y = v1;
                    *(float2*)(Cf + (size_t)r * N + col) = o;
                }
            }
        }
    }
}

// ---------------- attention: kv partial via tensor cores ----------------
// Block = (bh, n-chunk of 512). 4 warps; warp w owns d rows [16w,16w+16).
// kv[d][e] = sum_n k[n,d] * v[n,e]  via A=k^T (trans-ldmatrix), B=v^T (trans).
// ksum[d] via extra mma against an all-ones B fragment.
__global__ __launch_bounds__(128) void kv_part_kernel(
    const __half* __restrict__ qkvh, float* __restrict__ kvp, float* __restrict__ ksump)
{
    const int bx = blockIdx.x;          // 0..511
    const int bh = bx >> 3, chunk = bx & 7;
    const int b = bh >> 4, h = bh & 15;
    const int n0 = chunk * (NN / KVCHUNK);
    const __half* kbase = qkvh + (size_t)b * NN * QKVC + CC + h * DD;
    const __half* vbase = qkvh + (size_t)b * NN * QKVC + 2 * CC + h * DD;

    __shared__ __align__(16) char smm[32768];   // 2 stages x (k 8KB + v 8KB)
    const uint32_t sb = smem_u32(smm);

    const int tid = threadIdx.x;
    const int lane = tid & 31, w = tid >> 5;

    const int ch = tid & 7;
    const int rb0 = tid >> 3;            // 0..15
    uint32_t so[4]; size_t go[4];
    #pragma unroll
    for (int i = 0; i < 4; i++) {
        int r = rb0 + 16 * i;
        so[i] = (uint32_t)(r * 128) + (uint32_t)((ch ^ (r & 7)) << 4);
        go[i] = (size_t)r * QKVC + ch * 8;
    }

    auto issue = [&](int t) {
        if (t < 8) {
            uint32_t st = sb + (uint32_t)(t & 1) * 16384u;
            size_t base = (size_t)(n0 + t * 64) * QKVC;
            #pragma unroll
            for (int i = 0; i < 4; i++) {
                cp16(st + so[i],         kbase + base + go[i]);
                cp16(st + 8192u + so[i], vbase + base + go[i]);
            }
        }
        CP_COMMIT();
    };

    float acc[8][4];
    #pragma unroll
    for (int i = 0; i < 8; i++)
        #pragma unroll
        for (int j = 0; j < 4; j++) acc[i][j] = 0.f;
    float ks[4] = {0.f, 0.f, 0.f, 0.f};
    const uint32_t ones2[2] = {0x3C003C00u, 0x3C003C00u};

    issue(0);

    for (int t = 0; t < 8; t++) {
        CP_WAIT0();
        __syncthreads();
        issue(t + 1);

        const uint32_t st = sb + (uint32_t)(t & 1) * 16384u;
        #pragma unroll
        for (int ns = 0; ns < 4; ns++) {
            // A = k^T (d rows 16w..16w+16, n cols 16ns..): trans-load.
            // lane bit4 -> n-half, lane bit3 -> d-chunk-half.
            int rowA = ns * 16 + (lane & 7) + ((lane >> 4) & 1) * 8;
            uint32_t cA = (uint32_t)(2 * w + ((lane >> 3) & 1));
            uint32_t ak[4];
            ldmx4t(ak, st + (uint32_t)(rowA * 128) + ((cA ^ (rowA & 7)) << 4));

            mma16816(ks, ak, ones2);   // ksum: B = all-ones

            // B = v^T: lane bit3 -> n-half, lane bit4 -> e-chunk-half.
            int rowB = ns * 16 + (lane & 7) + ((lane >> 3) & 1) * 8;
            #pragma unroll
            for (int np = 0; np < 4; np++) {
                uint32_t cB = (uint32_t)(2 * np + ((lane >> 4) & 1));
                uint32_t bv[4];
                ldmx4t(bv, st + 8192u + (uint32_t)(rowB * 128) + ((cB ^ (rowB & 7)) << 4));
                mma16816(acc[2*np  ], ak, bv + 0);
                mma16816(acc[2*np+1], ak, bv + 2);
            }
        }
    }

    float* kvo = kvp + (size_t)bx * DD * DD;
    #pragma unroll
    for (int np = 0; np < 4; np++) {
        #pragma unroll
        for (int j = 0; j < 4; j++) {
            int d = 16 * w + (lane >> 2) + (j >> 1) * 8;
            int e = 16 * np + (lane & 3) * 2 + (j & 1);
            kvo[d * DD + e]     = acc[2*np  ][j];
            kvo[d * DD + e + 8] = acc[2*np+1][j];
        }
    }
    if ((lane & 3) == 0) {
        int d = 16 * w + (lane >> 2);
        ksump[bx * DD + d]     = ks[0];
        ksump[bx * DD + d + 8] = ks[2];
    }
}

// reduce partials; emit fp16 hi/lo state + fp32 ksum
__global__ __launch_bounds__(256) void kv_reduce_kernel(
    const float* __restrict__ kvp, const float* __restrict__ ksump,
    __half* __restrict__ kvh, __half* __restrict__ kvl, float* __restrict__ ksum)
{
    const int bh = blockIdx.x;
    const int tid = threadIdx.x;
    #pragma unroll
    for (int e = 0; e < 16; e++) {
        int idx = tid + e * 256;
        float s = 0.f;
        #pragma unroll
        for (int c = 0; c < KVCHUNK; c++)
            s += kvp[(size_t)(bh * KVCHUNK + c) * DD * DD + idx];
        __half hv = __float2half_rn(s);
        kvh[(size_t)bh * DD * DD + idx] = hv;
        kvl[(size_t)bh * DD * DD + idx] = __float2half_rn(s - __half2float(hv));
    }
    if (tid < DD) {
        float s = 0.f;
        #pragma unroll
        for (int c = 0; c < KVCHUNK; c++)
            s += ksump[(bh * KVCHUNK + c) * DD + tid];
        ksum[bh * DD + tid] = s;
    }
}

// ---------------- qout via tensor cores ----------------
// Block = (64-row n-tile, bh). 4 warps; warp w owns n rows [16w,16w+16).
// out[n][e] = (q[n,:] @ (kvh+kvl)[:,e]) * z[n];  A = q (non-trans), B = kv^T (trans).
__global__ __launch_bounds__(128) void qout_kernel(
    const __half* __restrict__ qkvh, const __half* __restrict__ kvh,
    const __half* __restrict__ kvl, const float* __restrict__ ksum,
    __half* __restrict__ ah)
{
    const int bh = blockIdx.y;
    const int b = bh >> 4, h = bh & 15;
    const int n0 = blockIdx.x * 64;

    // qs 0..8K, kvh 8..16K, kvl 16..24K, ksum 24K..+256, zden +256..+512
    __shared__ __align__(16) char smq[24576 + 512];
    const uint32_t sb = smem_u32(smq);
    float* ksm  = (float*)(smq + 24576);
    float* zden = (float*)(smq + 24576 + 256);

    const int tid = threadIdx.x;
    const int lane = tid & 31, w = tid >> 5;
    const __half* qbase = qkvh + (size_t)b * NN * QKVC + h * DD;

    const int ch = tid & 7;
    const int rb0 = tid >> 3;
    #pragma unroll
    for (int i = 0; i < 4; i++) {
        int r = rb0 + 16 * i;
        uint32_t so = (uint32_t)(r * 128) + (uint32_t)((ch ^ (r & 7)) << 4);
        cp16(sb + so,          qbase + (size_t)(n0 + r) * QKVC + ch * 8);
        cp16(sb + 8192u + so,  kvh + (size_t)bh * DD * DD + r * DD + ch * 8);
        cp16(sb + 16384u + so, kvl + (size_t)bh * DD * DD + r * DD + ch * 8);
    }
    CP_COMMIT();
    if (tid < DD) ksm[tid] = ksum[bh * DD + tid];
    CP_WAIT0();
    __syncthreads();

    // zden: per n-row scalar over d (fp32 ksum, fp16 q -> fp32)
    if (tid < 64) {
        int r = tid;
        float s = 0.f;
        #pragma unroll
        for (int d = 0; d < DD; d++) {
            uint32_t addr = (uint32_t)(r * 128) + ((((uint32_t)(d >> 3)) ^ (r & 7)) << 4) + (d & 7) * 2;
            __half qv = *(const __half*)(smq + addr);
            s += __half2float(qv) * ksm[d];
        }
        zden[r] = 1.f / (s + 1e-6f);
    }
    __syncthreads();

    float acc[8][4];
    #pragma unroll
    for (int i = 0; i < 8; i++)
        #pragma unroll
        for (int j = 0; j < 4; j++) acc[i][j] = 0.f;

    #pragma unroll
    for (int ds = 0; ds < 4; ds++) {
        // A = q: rows n (lane&15), chunk = d-step*2 + (lane>>4). Non-trans.
        int ra = 16 * w + (lane & 15);
        uint32_t cA = (uint32_t)(2 * ds + (lane >> 4));
        uint32_t aq[4];
        ldmx4(aq, sb + (uint32_t)(ra * 128) + ((cA ^ (ra & 7)) << 4));

        // B = kv^T: lane bit3 -> d-half, lane bit4 -> e-chunk-half. Trans.
        int rowB = ds * 16 + (lane & 7) + ((lane >> 3) & 1) * 8;
        #pragma unroll
        for (int np = 0; np < 4; np++) {
            uint32_t cB = (uint32_t)(2 * np + ((lane >> 4) & 1));
            uint32_t off = (uint32_t)(rowB * 128) + ((cB ^ (rowB & 7)) << 4);
            uint32_t bh2[4], bl2[4];
            ldmx4t(bh2, sb + 8192u + off);
            ldmx4t(bl2, sb + 16384u + off);
            mma16816(acc[2*np  ], aq, bh2 + 0);
            mma16816(acc[2*np+1], aq, bh2 + 2);
            mma16816(acc[2*np  ], aq, bl2 + 0);
            mma16816(acc[2*np+1], aq, bl2 + 2);
        }
    }

    #pragma unroll
    for (int np = 0; np < 4; np++) {
        #pragma unroll
        for (int jp = 0; jp < 2; jp++) {
            int rown = 16 * w + (lane >> 2) + jp * 8;
            float z = zden[rown];
            size_t obase = ((size_t)b * NN + n0 + rown) * CC + h * DD + 16 * np + (lane & 3) * 2;
            *(__half2*)(ah + obase) =
                __floats2half2_rn(acc[2*np][jp*2] * z, acc[2*np][jp*2+1] * z);
            *(__half2*)(ah + obase + 8) =
                __floats2half2_rn(acc[2*np+1][jp*2] * z, acc[2*np+1][jp*2+1] * z);
        }
    }
}

// ---------------------------------------------------------------------------
extern "C" void kernel_launch(void* const* d_in, const int* in_sizes, int n_in,
                              void* d_out, int out_size)
{
    const float* x     = (const float*)d_in[0];
    const float* Wqkv  = (const float*)d_in[1];
    const float* Wproj = (const float*)d_in[2];
    const float* bproj = (const float*)d_in[3];
    float* out = (float*)d_out;

    float *ksum_p, *kvp_p, *ksump_p;
    __half *qkvh, *xh, *ah, *wq, *wp, *kvh_p, *kvl_p;
    cudaGetSymbolAddress((void**)&qkvh, g_qkvh);
    cudaGetSymbolAddress((void**)&ksum_p, g_ksum);
    cudaGetSymbolAddress((void**)&kvp_p,  g_kvp);
    cudaGetSymbolAddress((void**)&ksump_p, g_ksump);
    cudaGetSymbolAddress((void**)&kvh_p, g_kvh);
    cudaGetSymbolAddress((void**)&kvl_p, g_kvl);
    cudaGetSymbolAddress((void**)&xh, g_xh);
    cudaGetSymbolAddress((void**)&ah, g_attn_h);
    cudaGetSymbolAddress((void**)&wq, g_wqkvT);
    cudaGetSymbolAddress((void**)&wp, g_wprojT);

    cudaFuncSetAttribute(gemm_mma<true, false, true>,
                         cudaFuncAttributeMaxDynamicSharedMemorySize, GEMM_SMEM);
    cudaFuncSetAttribute(gemm_mma<false, true, false>,
                         cudaFuncAttributeMaxDynamicSharedMemorySize, GEMM_SMEM);

    // x -> fp16
    {
        size_t n2 = (size_t)MTOT * CC / 2;
        cvt_f16<<<(unsigned)((n2 + 255) / 256), 256>>>(
            (const float2*)x, (__half2*)xh, n2);
    }
    // transpose weights to [N][K] fp16
    transpose_cvt<<<dim3(QKVC / 32, KDIM / 32), 256>>>(Wqkv, wq, KDIM, QKVC);
    transpose_cvt<<<dim3(CC / 32, KDIM / 32), 256>>>(Wproj, wp, KDIM, CC);

    // GEMM1: qkv = x @ W_qkv  (fused elu+1 on cols < 2048, fp16 out)
    gemm_mma<true, false, true><<<dim3(QKVC / 128, MTOT / 128), 128, GEMM_SMEM>>>(
        xh, wq, nullptr, qkvh, QKVC);

    // attention state (tensor-core partials, deterministic reduce) + output
    kv_part_kernel<<<BB * HH * KVCHUNK, 128>>>(qkvh, kvp_p, ksump_p);
    kv_reduce_kernel<<<BB * HH, 256>>>(kvp_p, ksump_p, kvh_p, kvl_p, ksum_p);
    qout_kernel<<<dim3(NN / 64, BB * HH), 128>>>(qkvh, kvh_p, kvl_p, ksum_p, ah);

    // GEMM2: out = attn @ W_proj + b_proj (fp32 out)
    gemm_mma<false, true, false><<<dim3(CC / 128, MTOT / 128), 128, GEMM_SMEM>>>(
        ah, wp, bproj, out, CC);
}